// round 1
// baseline (speedup 1.0000x reference)
#include <cuda_runtime.h>

// Problem dims (fixed for this problem instance)
#define BB   512
#define TT   100
#define II   700
#define HH   128
#define OO   20
#define NROWS (BB*TT)          // 51200 independent (b,t) rows for phase 1

// exp(-dt/tau) constants, fp32
#define ALPHA 0.81873075307798182f   // exp(-0.2)
#define BETA  0.90483741803595957f   // exp(-0.1)
#define LAM   0.95122942450071400f   // exp(-0.05)

// Scratch (device globals: allocation-free per harness rules)
static __device__ float4 g_W0T4[II * (HH/4)];          // W0^T: [i][h], 358 KB
static __device__ float4 g_U4[(size_t)NROWS * (HH/4)]; // U[b,t,h] = (x_t @ W0^T), 26 MB

// ---------------------------------------------------------------------------
// K1: transpose W0 (H,I) row-major -> W0T (I,H)
// ---------------------------------------------------------------------------
__global__ void k_transpose_w0(const float* __restrict__ W0) {
    int idx = blockIdx.x * blockDim.x + threadIdx.x;
    if (idx < II * HH) {
        int i = idx >> 7;          // 0..699
        int h = idx & 127;
        ((float*)g_W0T4)[idx] = W0[h * II + i];   // coalesced write
    }
}

// ---------------------------------------------------------------------------
// K2: phase 1 — U[r,h] = sum_{i: x[r,i]=1} W0T[i,h]
// One warp per row r = b*T + t. Thread covers 4 h via float4.
// Spikes are exactly 0.0/1.0 so add == multiply-accumulate exactly.
// ---------------------------------------------------------------------------
__global__ void __launch_bounds__(256) k_phase1(const float* __restrict__ X) {
    int warp = (blockIdx.x * 256 + threadIdx.x) >> 5;
    int lane = threadIdx.x & 31;
    if (warp >= NROWS) return;

    const float* xr = X + (size_t)warp * II;
    const float4* w4 = g_W0T4;
    float4 acc = make_float4(0.f, 0.f, 0.f, 0.f);

    for (int c = 0; c < II; c += 32) {
        int i0 = c + lane;
        float xv = (i0 < II) ? __ldg(xr + i0) : 0.0f;
        unsigned m = __ballot_sync(0xffffffffu, xv != 0.0f);
        while (m) {
            int j = __ffs(m) - 1;
            m &= m - 1;
            float4 w = w4[(c + j) * 32 + lane];
            acc.x += w.x; acc.y += w.y; acc.z += w.z; acc.w += w.w;
        }
    }
    g_U4[(size_t)warp * 32 + lane] = acc;
}

// ---------------------------------------------------------------------------
// K3: phase 2 — per-sample recurrent LIF + readout.
// 4 samples per CTA (512 threads). Thread = one neuron h of one sample.
// W1^T, V1^T (stride 129: conflict-free), Wr^T in dynamic SMEM.
// Spike masks exchanged via ballot + SMEM + per-group named barriers.
// ---------------------------------------------------------------------------
__device__ __forceinline__ void acc_rows(float& acc, unsigned m, int base,
                                         const float* Wt, int h) {
    while (m) {
        int j = __ffs(m) - 1;
        m &= m - 1;
        acc += Wt[(base + j) * 129 + h];
    }
}

__device__ __forceinline__ void acc_ro(float& acc, unsigned m, int base,
                                       const float* Wrs, int o) {
    while (m) {
        int j = __ffs(m) - 1;
        m &= m - 1;
        acc += Wrs[(base + j) * OO + o];
    }
}

__global__ void __launch_bounds__(512, 1) k_phase2(
    const float* __restrict__ W1, const float* __restrict__ V1,
    const float* __restrict__ Wr, const float* __restrict__ br,
    float* __restrict__ out)
{
    extern __shared__ float sm[];
    float* W1s = sm;                       // 128*129 floats
    float* V1s = W1s + HH * 129;           // 128*129 floats
    float* Wrs = V1s + HH * 129;           // 128*20  floats
    unsigned* kmasks = (unsigned*)(Wrs + HH * OO);  // 4 groups * 8 words

    // Load weights transposed into SMEM. Reads coalesced; 129-stride writes
    // are conflict-free ((j*129+h)%32 varies with j).
    for (int idx = threadIdx.x; idx < HH * HH; idx += 512) {
        int h = idx >> 7, j = idx & 127;
        W1s[j * 129 + h] = W1[idx];
        V1s[j * 129 + h] = V1[idx];
    }
    for (int idx = threadIdx.x; idx < OO * HH; idx += 512) {
        int o = idx >> 7, j = idx & 127;
        Wrs[j * OO + o] = Wr[idx];
    }
    __syncthreads();

    int g    = threadIdx.x >> 7;          // sample group 0..3
    int h    = threadIdx.x & 127;         // neuron index
    int lane = threadIdx.x & 31;
    int wig  = (threadIdx.x >> 5) & 3;    // warp within group
    int b    = blockIdx.x * 4 + g;
    unsigned* k0m = kmasks + g * 8;
    unsigned* k1m = k0m + 4;
    int barid = g + 1;                    // named barriers 1..4, 128 threads

    float s0 = 0.f, m0 = 0.f, s1 = 0.f, m1 = 0.f, rp = 0.f;
    float brv = (h < OO) ? br[h] : 0.f;
    unsigned p0 = 0, p1 = 0, p2 = 0, p3 = 0;   // previous-step k1 masks

    const float* Ub  = (const float*)g_U4 + (size_t)b * TT * HH;
    float*       outb = out + (size_t)b * TT * OO;

    float u = Ub[h];   // prefetch t=0
    for (int t = 0; t < TT; t++) {
        float u_next = (t + 1 < TT) ? Ub[(t + 1) * HH + h] : 0.f;

        // Layer 0 (feedforward LIF)
        s0 = ALPHA * s0 + u;
        m0 = BETA * m0 + s0;
        bool sp0 = m0 > 1.0f;
        if (sp0) m0 = 0.f;

        unsigned bm = __ballot_sync(0xffffffffu, sp0);
        if (lane == 0) k0m[wig] = bm;
        asm volatile("bar.sync %0, %1;" :: "r"(barid), "r"(128) : "memory");

        // Layer 1 (recurrent LIF): k0 of THIS step, k1 of PREVIOUS step
        float accW = 0.f;
        acc_rows(accW, k0m[0], 0,  W1s, h);
        acc_rows(accW, k0m[1], 32, W1s, h);
        acc_rows(accW, k0m[2], 64, W1s, h);
        acc_rows(accW, k0m[3], 96, W1s, h);
        float accV = 0.f;
        acc_rows(accV, p0, 0,  V1s, h);
        acc_rows(accV, p1, 32, V1s, h);
        acc_rows(accV, p2, 64, V1s, h);
        acc_rows(accV, p3, 96, V1s, h);
        s1 = (ALPHA * s1 + accW) + accV;
        m1 = BETA * m1 + s1;
        bool sp1 = m1 > 1.0f;
        if (sp1) m1 = 0.f;

        unsigned bm1 = __ballot_sync(0xffffffffu, sp1);
        if (lane == 0) k1m[wig] = bm1;
        asm volatile("bar.sync %0, %1;" :: "r"(barid), "r"(128) : "memory");
        p0 = k1m[0]; p1 = k1m[1]; p2 = k1m[2]; p3 = k1m[3];

        // Leaky readout with the NEW k1
        if (h < OO) {
            float racc = brv;
            acc_ro(racc, p0, 0,  Wrs, h);
            acc_ro(racc, p1, 32, Wrs, h);
            acc_ro(racc, p2, 64, Wrs, h);
            acc_ro(racc, p3, 96, Wrs, h);
            rp = LAM * rp + (1.0f - LAM) * racc;
            outb[t * OO + h] = rp;
        }
        u = u_next;
    }
}

// ---------------------------------------------------------------------------
// Launch
// ---------------------------------------------------------------------------
extern "C" void kernel_launch(void* const* d_in, const int* in_sizes, int n_in,
                              void* d_out, int out_size) {
    (void)in_sizes; (void)n_in; (void)out_size;
    const float* X  = (const float*)d_in[0];  // spike_trains (B,T,I)
    const float* W0 = (const float*)d_in[1];  // (H,I)
    const float* W1 = (const float*)d_in[2];  // (H,H)
    const float* V1 = (const float*)d_in[3];  // (H,H)
    const float* Wr = (const float*)d_in[4];  // (O,H)
    const float* br = (const float*)d_in[5];  // (O,)
    float* out = (float*)d_out;               // (B,T,O)

    k_transpose_w0<<<(II * HH + 255) / 256, 256>>>(W0);
    k_phase1<<<NROWS / 8, 256>>>(X);

    const size_t smem2 = (size_t)(2 * HH * 129 + HH * OO) * sizeof(float)
                       + 4 * 8 * sizeof(unsigned);
    cudaFuncSetAttribute(k_phase2, cudaFuncAttributeMaxDynamicSharedMemorySize,
                         (int)smem2);
    k_phase2<<<BB / 4, 512, smem2>>>(W1, V1, Wr, br, out);
}